// round 17
// baseline (speedup 1.0000x reference)
#include <cuda_runtime.h>
#include <math.h>
#include <stdint.h>

#define T_LEN 8192
#define T4 (T_LEN / 4)
#define RADIUS 12                 // truncation rel-err ~9e-5 << 1e-3
#define NTAPS (RADIUS + 1)        // 13 one-sided taps incl. x=0
#define CLUSTER 8
#define THREADS 512
#define OPT 2                     // outputs per thread
#define PER_CTA (THREADS * OPT)   // 1024
#define MVEC (PER_CTA / 4 + 8)    // 264 float4: floats [base-16 .. base+1039]
#define INV_SQRT_2PI 0.39894228f
#define NOISE_SIGMA 0.01f

__device__ __forceinline__ uint32_t smem_u32(const void* p) {
    uint32_t a;
    asm("{ .reg .u64 t; cvta.to.shared.u64 t, %1; cvt.u32.u64 %0, t; }"
        : "=r"(a) : "l"(p));
    return a;
}
// two independent warp sums, interleaved shfl chains
__device__ __forceinline__ void warp_sum2(float& a, float& b) {
    #pragma unroll
    for (int o = 16; o > 0; o >>= 1) {
        a += __shfl_xor_sync(0xffffffffu, a, o);
        b += __shfl_xor_sync(0xffffffffu, b, o);
    }
}

__global__ void __launch_bounds__(THREADS, 1) __cluster_dims__(CLUSTER, 1, 1)
k_fused(const float4* __restrict__ X4,
        const float* __restrict__ weight,
        const float* __restrict__ sigma_min,
        const float* __restrict__ sigma_max,
        const float2* __restrict__ noise2,
        float2* __restrict__ out2) {
    __shared__ float4 sM4[MVEC];          // mask window (X is already {0,1})
    __shared__ float sG[NTAPS];
    __shared__ __align__(8) unsigned long long spk[16];  // packed {mx,mn} per warp
    __shared__ __align__(8) float2 slot[CLUSTER];        // {lo,hi} per CTA

    const int tid = threadIdx.x;
    const int wid = tid >> 5;             // 0..15
    const int lid = tid & 31;
    uint32_t rank;
    asm("mov.u32 %0, %%cluster_ctarank;" : "=r"(rank));
    const int vbase = (int)rank * (PER_CTA / 4);    // float4 base
    const int hbase = (int)rank * (PER_CTA / 2);    // float2 base

    // ---- hoist remote DSMEM address off the tail (warp 0, lanes 0-7) ----
    uint32_t rslot = 0;
    if (wid == 0 && lid < CLUSTER) {
        uint32_t a = smem_u32(&slot[rank]);
        asm volatile("mapa.shared::cluster.u32 %0, %1, %2;"
                     : "=r"(rslot) : "r"(a), "r"(lid));
    }
    float2* outp = &out2[hbase + tid];    // epilogue address ready early

    // ---- long-latency loads first ----
    float2 nz2 = noise2[hbase + tid];
    if (tid < MVEC) {                     // 512 threads cover 264 items in one pass
        int v4 = vbase - 4 + tid;
        float4 xv = make_float4(0.f, 0.f, 0.f, 0.f);
        if (v4 >= 0 && v4 < T4) xv = X4[v4];
        sM4[tid] = xv;
    }
    nz2.x *= NOISE_SIGMA; nz2.y *= NOISE_SIGMA;

    // ---- sG: warp wid computes tap wid (warps 0..12), 4 sigmas per lane ----
    if (wid < NTAPS) {
        float smn_v = sigma_min[0];
        float smx_v = sigma_max[0];
        float e0 = __expf(weight[lid]);
        float e1 = __expf(weight[lid + 32]);
        float e2 = __expf(weight[lid + 64]);
        float e3 = __expf(weight[lid + 96]);

        float step = (smx_v - smn_v) * (1.0f / 127.0f);
        float s0 = fabsf(smn_v + (float)lid * step);
        float s1 = fabsf(smn_v + (float)(lid + 32) * step);
        float s2 = fabsf(smn_v + (float)(lid + 64) * step);
        float s3 = fabsf(smn_v + (float)(lid + 96) * step);

        float xx = (float)wid; xx *= xx;
        float v = e0 * INV_SQRT_2PI / s0 * __expf(-xx * (0.5f / (s0 * s0)))
                + e1 * INV_SQRT_2PI / s1 * __expf(-xx * (0.5f / (s1 * s1)))
                + e2 * INV_SQRT_2PI / s2 * __expf(-xx * (0.5f / (s2 * s2)))
                + e3 * INV_SQRT_2PI / s3 * __expf(-xx * (0.5f / (s3 * s3)));
        float denom = e0 + e1 + e2 + e3;

        warp_sum2(v, denom);
        if (lid == 0) sG[wid] = v * __fdividef(1.0f, denom);
    }
    __syncthreads();                      // sM4 + sG ready

    // ---- conv: 2 outputs/thread, 28-float window via 14 LDS.64 ----
    float c[NTAPS];
    #pragma unroll
    for (int x = 0; x < NTAPS; ++x) c[x] = sG[x];

    // wrf[m] = X[base + 2*tid - 14 + m], m = 0..27
    float wrf[28];
    {
        const float2* s2p = (const float2*)sM4;   // s2p[i] = floats X[base-16+2i]
        #pragma unroll
        for (int k = 0; k < 14; ++k) {
            float2 v = s2p[tid + 1 + k];
            wrf[2 * k] = v.x; wrf[2 * k + 1] = v.y;
        }
    }

    // output t = base + 2*tid + j; mask[t-1+d] = wrf[13 + j + d]
    float acc[OPT];
    {
        float nzs[2] = {nz2.x, nz2.y};
        #pragma unroll
        for (int j = 0; j < OPT; ++j) {
            float a0 = fmaf(c[0], wrf[13 + j], nzs[j]);
            float a1 = 0.0f;
            #pragma unroll
            for (int x = 1; x < NTAPS; x += 2) {
                a0 = fmaf(c[x], wrf[13 + j - x] + wrf[13 + j + x], a0);
                if (x + 1 < NTAPS)
                    a1 = fmaf(c[x + 1], wrf[12 + j - x] + wrf[14 + j + x], a1);
            }
            acc[j] = a0 + a1;
        }
    }

    // ---- min/max: thread -> warp -> packed block partial ----
    float mn = fminf(acc[0], acc[1]);
    float mx = fmaxf(acc[0], acc[1]);
    #pragma unroll
    for (int o = 16; o > 0; o >>= 1) {
        mn = fminf(mn, __shfl_xor_sync(0xffffffffu, mn, o));
        mx = fmaxf(mx, __shfl_xor_sync(0xffffffffu, mx, o));
    }
    if (lid == 0)
        spk[wid] = ((unsigned long long)__float_as_uint(mx) << 32) | __float_as_uint(mn);
    __syncthreads();

    if (wid == 0) {
        unsigned long long pw = spk[lid & 15];    // one LDS.64 per lane
        float bmn = __uint_as_float((unsigned)pw);
        float bmx = __uint_as_float((unsigned)(pw >> 32));
        #pragma unroll
        for (int o = 8; o > 0; o >>= 1) {
            bmn = fminf(bmn, __shfl_xor_sync(0xffffffffu, bmn, o));
            bmx = fmaxf(bmx, __shfl_xor_sync(0xffffffffu, bmx, o));
        }
        if (lid < CLUSTER) {              // one 64-bit DSMEM store per peer
            unsigned long long pk =
                ((unsigned long long)__float_as_uint(bmx) << 32) | __float_as_uint(bmn);
            asm volatile("st.shared::cluster.u64 [%0], %1;" :: "r"(rslot), "l"(pk) : "memory");
        }
    }

    // ---- cluster barrier: releases DSMEM stores, acquires peer stores ----
    asm volatile("barrier.cluster.arrive.aligned;" ::: "memory");
    asm volatile("barrier.cluster.wait.aligned;" ::: "memory");

    float L = slot[0].x, H = slot[0].y;
    #pragma unroll
    for (int j = 1; j < CLUSTER; ++j) {
        L = fminf(L, slot[j].x);
        H = fmaxf(H, slot[j].y);
    }
    float inv = __fdividef(1.0f, H - L);
    *outp = make_float2((acc[0] - L) * inv, (acc[1] - L) * inv);
}

extern "C" void kernel_launch(void* const* d_in, const int* in_sizes, int n_in,
                              void* d_out, int out_size) {
    const float4* X4  = (const float4*)d_in[0];
    const float* wgt  = (const float*)d_in[1];
    const float* smin = (const float*)d_in[2];
    const float* smax = (const float*)d_in[3];
    const float2* nz2 = (const float2*)d_in[4];
    float2* out2 = (float2*)d_out;

    k_fused<<<CLUSTER, THREADS>>>(X4, wgt, smin, smax, nz2, out2);
}